// round 4
// baseline (speedup 1.0000x reference)
#include <cuda_runtime.h>
#include <cuda_bf16.h>
#include <cstdint>

// ============================================================================
// QuantizedLinear: y[M,N] = x[M,K] @ Wq[N,K]^T * scale + bias
// M=16384, N=4096, K=4096.
// R3: two-plane int8 IMMA path.
//   - W is integer 0..126 -> exact s8
//   - x row-quantized to two s8 planes: x ~= s1*a1 + (s1/254)*a2  (err<=s1/508)
//   - mma.m16n8k32 s8 -> s32 accumulators (exact integer arithmetic)
//   - cp.async.bulk + mbarrier 4-stage pipeline, pre-swizzled global tiles
// ============================================================================

#define M_TOTAL  16384
#define N_TOTAL  4096
#define K_TOTAL  4096

#define TILE_M   128
#define TILE_N   128
#define TILE_K   128                     // 128 int8 = 128 B/row = SW128 atom
#define NUM_KT   (K_TOTAL / TILE_K)      // 32
#define STAGES   4

#define A_TILE_BYTES  (TILE_M * TILE_K)  // 16384 (per plane)
#define B_TILE_BYTES  (TILE_N * TILE_K)  // 16384
#define STAGE_BYTES   (2 * A_TILE_BYTES + B_TILE_BYTES)  // 49152

#define TILES_M  (M_TOTAL / TILE_M)      // 128
#define TILES_N  (N_TOTAL / TILE_N)      // 32

#define INV254   (1.0f / 254.0f)

// Scratch (static device arrays, no allocs). Tiled [t][kt][128x128] SW128.
__device__ uint4 g_xa1[(size_t)M_TOTAL * K_TOTAL / 16];  // 64 MB s8 plane 1
__device__ uint4 g_xa2[(size_t)M_TOTAL * K_TOTAL / 16];  // 64 MB s8 plane 2
__device__ uint4 g_wq8[(size_t)N_TOTAL * K_TOTAL / 16];  // 16 MB s8 weights
__device__ float g_s1[M_TOTAL];                          // per-row scale

// ---------------------------------------------------------------------------
// PTX helpers (base ISA only)
// ---------------------------------------------------------------------------
__device__ __forceinline__ uint32_t smem_u32(const void* p) {
    uint32_t a;
    asm("{ .reg .u64 t; cvta.to.shared.u64 t, %1; cvt.u32.u64 %0, t; }"
        : "=r"(a) : "l"(p));
    return a;
}
__device__ __forceinline__ void mbar_init(uint32_t mbar, uint32_t count) {
    asm volatile("mbarrier.init.shared.b64 [%0], %1;" :: "r"(mbar), "r"(count) : "memory");
}
__device__ __forceinline__ void mbar_expect_tx(uint32_t mbar, uint32_t bytes) {
    asm volatile("mbarrier.arrive.expect_tx.shared.b64 _, [%0], %1;"
                 :: "r"(mbar), "r"(bytes) : "memory");
}
__device__ __forceinline__ void mbar_arrive(uint32_t mbar) {
    asm volatile("mbarrier.arrive.shared.b64 _, [%0];" :: "r"(mbar) : "memory");
}
__device__ __forceinline__ void mbar_wait(uint32_t mbar, uint32_t parity) {
    asm volatile(
        "{\n\t.reg .pred P;\n\t"
        "WAITLOOP_%=:\n\t"
        "mbarrier.try_wait.parity.acquire.cta.shared::cta.b64 P, [%0], %1, 0x989680;\n\t"
        "@!P bra WAITLOOP_%=;\n\t}"
        :: "r"(mbar), "r"(parity) : "memory");
}
__device__ __forceinline__ void bulk_g2s(uint32_t dst, const void* src,
                                         uint32_t bytes, uint32_t mbar) {
    asm volatile(
        "cp.async.bulk.shared::cta.global.mbarrier::complete_tx::bytes [%0], [%1], %2, [%3];"
        :: "r"(dst), "l"(src), "r"(bytes), "r"(mbar) : "memory");
}
#define FENCE_PROXY_ASYNC() asm volatile("fence.proxy.async;" ::: "memory")

__device__ __forceinline__ void ldsm_x4(uint32_t* r, uint32_t addr) {
    asm volatile("ldmatrix.sync.aligned.m8n8.x4.shared.b16 {%0,%1,%2,%3}, [%4];"
                 : "=r"(r[0]), "=r"(r[1]), "=r"(r[2]), "=r"(r[3]) : "r"(addr));
}
__device__ __forceinline__ void imma16832(int* c, const uint32_t* a, const uint32_t* b) {
    asm volatile(
        "mma.sync.aligned.m16n8k32.row.col.s32.s8.s8.s32 "
        "{%0,%1,%2,%3}, {%4,%5,%6,%7}, {%8,%9}, {%0,%1,%2,%3};"
        : "+r"(c[0]), "+r"(c[1]), "+r"(c[2]), "+r"(c[3])
        : "r"(a[0]), "r"(a[1]), "r"(a[2]), "r"(a[3]), "r"(b[0]), "r"(b[1]));
}

__device__ __forceinline__ uint32_t sw128(uint32_t off) {
    return off ^ ((off >> 3) & 0x70);
}
__device__ __forceinline__ uint32_t pack8(int i0, int i1, int i2, int i3) {
    return (uint32_t)(i0 & 255) | ((uint32_t)(i1 & 255) << 8) |
           ((uint32_t)(i2 & 255) << 16) | ((uint32_t)(i3 & 255) << 24);
}

// ---------------------------------------------------------------------------
// Prep 1: per-row two-plane int8 quantization of x.
// One block per row (4096 floats). Each thread: 16 elements.
// ---------------------------------------------------------------------------
__global__ void __launch_bounds__(256) split_x_kernel(const float* __restrict__ x) {
    __shared__ float red[8];
    __shared__ float s_bcast;

    int m = blockIdx.x;
    int t = threadIdx.x;
    const float4* xr = reinterpret_cast<const float4*>(x + ((size_t)m << 12));

    float4 v[4];
#pragma unroll
    for (int i = 0; i < 4; i++) v[i] = xr[t * 4 + i];

    // amax reduction
    float amax = 0.f;
#pragma unroll
    for (int i = 0; i < 4; i++) {
        amax = fmaxf(amax, fmaxf(fmaxf(fabsf(v[i].x), fabsf(v[i].y)),
                                 fmaxf(fabsf(v[i].z), fabsf(v[i].w))));
    }
#pragma unroll
    for (int o = 16; o > 0; o >>= 1)
        amax = fmaxf(amax, __shfl_xor_sync(0xffffffffu, amax, o));
    if ((t & 31) == 0) red[t >> 5] = amax;
    __syncthreads();
    if (t == 0) {
        float a = red[0];
#pragma unroll
        for (int i = 1; i < 8; i++) a = fmaxf(a, red[i]);
        s_bcast = fmaxf(a, 1e-20f);
        g_s1[m] = s_bcast / 127.0f;
    }
    __syncthreads();

    float s1     = s_bcast / 127.0f;
    float inv_s1 = 127.0f / s_bcast;
    float inv_s2 = inv_s1 * 254.0f;

    int q1[16], q2[16];
    const float* f = reinterpret_cast<const float*>(v);
#pragma unroll
    for (int i = 0; i < 16; i++) {
        float a1f = rintf(f[i] * inv_s1);
        a1f = fminf(fmaxf(a1f, -127.f), 127.f);
        float r   = fmaf(-s1, a1f, f[i]);
        float a2f = rintf(r * inv_s2);
        a2f = fminf(fmaxf(a2f, -127.f), 127.f);
        q1[i] = (int)a1f;
        q2[i] = (int)a2f;
    }

    // write 16 bytes into tiled SW128 layout
    int k   = t * 16;
    int mt  = m >> 7, row = m & 127;
    int kt  = k >> 7, kin = k & 127;
    size_t base = ((size_t)(mt * NUM_KT + kt)) * A_TILE_BYTES;
    uint32_t off = sw128((uint32_t)(row * 128 + kin));

    *reinterpret_cast<uint4*>(reinterpret_cast<char*>(g_xa1) + base + off) =
        make_uint4(pack8(q1[0], q1[1], q1[2], q1[3]),   pack8(q1[4], q1[5], q1[6], q1[7]),
                   pack8(q1[8], q1[9], q1[10], q1[11]), pack8(q1[12], q1[13], q1[14], q1[15]));
    *reinterpret_cast<uint4*>(reinterpret_cast<char*>(g_xa2) + base + off) =
        make_uint4(pack8(q2[0], q2[1], q2[2], q2[3]),   pack8(q2[4], q2[5], q2[6], q2[7]),
                   pack8(q2[8], q2[9], q2[10], q2[11]), pack8(q2[12], q2[13], q2[14], q2[15]));
}

// ---------------------------------------------------------------------------
// Prep 2: weight int32 (0..126) -> s8 (exact), tiled [nt][kt][128x128] SW128.
// ---------------------------------------------------------------------------
__global__ void __launch_bounds__(256) conv_w_kernel(const int* __restrict__ wq) {
    uint32_t gid = blockIdx.x * 256u + threadIdx.x;   // N*K/16 threads
    int n = gid >> 8;
    int k = (gid & 255) << 4;

    const int4* wp = reinterpret_cast<const int4*>(wq + ((size_t)n << 12) + k);
    uint32_t pk[4];
#pragma unroll
    for (int i = 0; i < 4; i++) {
        int4 a = wp[i];
        pk[i] = pack8(a.x, a.y, a.z, a.w);
    }

    int nt = n >> 7, row = n & 127;
    int kt = k >> 7, kin = k & 127;
    size_t base = ((size_t)(nt * NUM_KT + kt)) * B_TILE_BYTES;
    uint32_t off = sw128((uint32_t)(row * 128 + kin));

    *reinterpret_cast<uint4*>(reinterpret_cast<char*>(g_wq8) + base + off) =
        make_uint4(pk[0], pk[1], pk[2], pk[3]);
}

// ---------------------------------------------------------------------------
// GEMM: 128x128 output tile per CTA. 8 consumer warps (32x64 each, 4Mx2N),
// 1 producer warp. 4-stage bulk-copy pipeline. Two s32 accumulator planes.
// ---------------------------------------------------------------------------
#define NTHREADS      288
#define SMEM_RAW_BYTES (1024 + 1024 + STAGES * STAGE_BYTES)

__global__ void __launch_bounds__(NTHREADS, 1)
gemm_kernel(float* __restrict__ out, const float* __restrict__ scale,
            const float* __restrict__ bias) {
    extern __shared__ char smem_raw[];
    uint32_t sb = (smem_u32(smem_raw) + 1023u) & ~1023u;

    const int tid = threadIdx.x;
    const int wid = tid >> 5;
    const int lid = tid & 31;

    // L2-friendly tile grouping: 4 m-tiles x 32 n-tiles per group of 128 CTAs
    int bid = blockIdx.x;
    int grp = bid >> 7;
    int r   = bid & 127;
    int mt  = (grp << 2) + (r & 3);
    int nt  = r >> 2;

    const uint32_t FULL_BAR  = sb;          // 4 x 8B
    const uint32_t EMPTY_BAR = sb + 64;     // 4 x 8B
    const uint32_t DATA      = sb + 1024;

    if (tid == 0) {
#pragma unroll
        for (int s = 0; s < STAGES; s++) {
            mbar_init(FULL_BAR  + s * 8, 1);
            mbar_init(EMPTY_BAR + s * 8, 8);
        }
        FENCE_PROXY_ASYNC();
    }
    __syncthreads();

    // ---------------- Producer warp ----------------
    if (wid == 8) {
        if (lid == 0) {
            const char* xa1 = reinterpret_cast<const char*>(g_xa1) +
                              (size_t)mt * NUM_KT * A_TILE_BYTES;
            const char* xa2 = reinterpret_cast<const char*>(g_xa2) +
                              (size_t)mt * NUM_KT * A_TILE_BYTES;
            const char* wq8 = reinterpret_cast<const char*>(g_wq8) +
                              (size_t)nt * NUM_KT * B_TILE_BYTES;

            auto issue = [&](int s, int kt) {
                uint32_t fb = FULL_BAR + s * 8;
                uint32_t d  = DATA + s * STAGE_BYTES;
                mbar_expect_tx(fb, STAGE_BYTES);
                bulk_g2s(d,                    xa1 + (size_t)kt * A_TILE_BYTES, A_TILE_BYTES, fb);
                bulk_g2s(d + A_TILE_BYTES,     xa2 + (size_t)kt * A_TILE_BYTES, A_TILE_BYTES, fb);
                bulk_g2s(d + 2 * A_TILE_BYTES, wq8 + (size_t)kt * B_TILE_BYTES, B_TILE_BYTES, fb);
            };

            issue(0, 0); issue(1, 1); issue(2, 2); issue(3, 3);
            int ep[STAGES] = {0, 0, 0, 0};
            for (int kt = STAGES; kt < NUM_KT; kt++) {
                int s = kt % STAGES;
                mbar_wait(EMPTY_BAR + s * 8, ep[s]); ep[s] ^= 1;
                issue(s, kt);
            }
        }
        return;
    }

    // ---------------- Consumer warps ----------------
    const int warp_m = wid & 3;          // 4 warps over M: 32 rows each
    const int warp_n = wid >> 2;         // 2 warps over N: 64 cols each

    // Per-lane swizzled SMEM offsets (kstep 0). K advance = XOR ks*32.
    uint32_t a_off[2], b_off[4];
#pragma unroll
    for (int mf = 0; mf < 2; mf++) {
        int row = warp_m * 32 + mf * 16 + (lid & 15);
        a_off[mf] = sw128((uint32_t)(row * 128 + (lid >> 4) * 16));
    }
#pragma unroll
    for (int p = 0; p < 4; p++) {
        int nrow = warp_n * 64 + p * 16 + (lid & 7) + ((lid >> 4) & 1) * 8;
        b_off[p] = sw128((uint32_t)(nrow * 128 + ((lid >> 3) & 1) * 16));
    }

    int acc1[2][8][4], acc2[2][8][4];
#pragma unroll
    for (int mf = 0; mf < 2; mf++)
#pragma unroll
        for (int nf = 0; nf < 8; nf++)
#pragma unroll
            for (int i = 0; i < 4; i++) { acc1[mf][nf][i] = 0; acc2[mf][nf][i] = 0; }

    int fp[STAGES] = {0, 0, 0, 0};

#pragma unroll 1
    for (int kt = 0; kt < NUM_KT; kt++) {
        int s = kt % STAGES;
        mbar_wait(FULL_BAR + s * 8, fp[s]); fp[s] ^= 1;

        uint32_t a1b = DATA + s * STAGE_BYTES;
        uint32_t a2b = a1b + A_TILE_BYTES;
        uint32_t bbb = a2b + A_TILE_BYTES;

#pragma unroll
        for (int ks = 0; ks < 4; ks++) {
            uint32_t kb = ks * 32;      // XOR into swizzled offset (bits 5-6)
            uint32_t f1[2][4], f2[2][4], bf[4][4];
            ldsm_x4(f1[0], a1b + (a_off[0] ^ kb));
            ldsm_x4(f1[1], a1b + (a_off[1] ^ kb));
            ldsm_x4(f2[0], a2b + (a_off[0] ^ kb));
            ldsm_x4(f2[1], a2b + (a_off[1] ^ kb));
            ldsm_x4(bf[0], bbb + (b_off[0] ^ kb));
            ldsm_x4(bf[1], bbb + (b_off[1] ^ kb));
            ldsm_x4(bf[2], bbb + (b_off[2] ^ kb));
            ldsm_x4(bf[3], bbb + (b_off[3] ^ kb));

#pragma unroll
            for (int mf = 0; mf < 2; mf++)
#pragma unroll
                for (int nf = 0; nf < 8; nf++) {
                    const uint32_t* bp = &bf[nf >> 1][(nf & 1) * 2];
                    imma16832(acc1[mf][nf], f1[mf], bp);
                    imma16832(acc2[mf][nf], f2[mf], bp);
                }
        }

        __syncwarp();
        if (lid == 0) mbar_arrive(EMPTY_BAR + s * 8);
    }

    // ------------- Epilogue: y = scale*s1[m]*(acc1 + acc2/254) + bias -------
    float scl = __ldg(scale);
    int row0 = (mt << 7) + warp_m * 32 + (lid >> 2);
    int col0 = (nt << 7) + warp_n * 64 + (lid & 3) * 2;

    float sr[2][2];   // [mf][half]: rows row0+mf*16, row0+mf*16+8
#pragma unroll
    for (int mf = 0; mf < 2; mf++) {
        sr[mf][0] = scl * __ldg(&g_s1[row0 + mf * 16]);
        sr[mf][1] = scl * __ldg(&g_s1[row0 + mf * 16 + 8]);
    }

#pragma unroll
    for (int nf = 0; nf < 8; nf++) {
        int col = col0 + nf * 8;
        float2 bv = __ldg(reinterpret_cast<const float2*>(bias + col));
#pragma unroll
        for (int mf = 0; mf < 2; mf++) {
            int ra = row0 + mf * 16;
            float c0 = (float)acc1[mf][nf][0] + (float)acc2[mf][nf][0] * INV254;
            float c1 = (float)acc1[mf][nf][1] + (float)acc2[mf][nf][1] * INV254;
            float c2 = (float)acc1[mf][nf][2] + (float)acc2[mf][nf][2] * INV254;
            float c3 = (float)acc1[mf][nf][3] + (float)acc2[mf][nf][3] * INV254;
            float2 o0, o1;
            o0.x = sr[mf][0] * c0 + bv.x;
            o0.y = sr[mf][0] * c1 + bv.y;
            o1.x = sr[mf][1] * c2 + bv.x;
            o1.y = sr[mf][1] * c3 + bv.y;
            *reinterpret_cast<float2*>(out + ((size_t)ra << 12)       + col) = o0;
            *reinterpret_cast<float2*>(out + ((size_t)(ra + 8) << 12) + col) = o1;
        }
    }
}

// ---------------------------------------------------------------------------
// Launch
// ---------------------------------------------------------------------------
extern "C" void kernel_launch(void* const* d_in, const int* in_sizes, int n_in,
                              void* d_out, int out_size) {
    const float* x     = (const float*)d_in[0];   // [4,4096,4096] fp32
    const int*   wq    = (const int*)  d_in[1];   // [4096,4096]   int32
    const float* scale = (const float*)d_in[2];   // [1]           fp32
    const float* bias  = (const float*)d_in[3];   // [4096]        fp32
    float*       out   = (float*)d_out;           // [4,4096,4096] fp32

    split_x_kernel<<<M_TOTAL, 256>>>(x);
    conv_w_kernel <<<(N_TOTAL * (K_TOTAL / 16)) / 256, 256>>>(wq);

    cudaFuncSetAttribute(gemm_kernel, cudaFuncAttributeMaxDynamicSharedMemorySize,
                         SMEM_RAW_BYTES);
    gemm_kernel<<<TILES_M * TILES_N, NTHREADS, SMEM_RAW_BYTES>>>(out, scale, bias);
}

// round 5
// speedup vs baseline: 3.4586x; 3.4586x over previous
#include <cuda_runtime.h>
#include <cuda_fp16.h>
#include <cstdint>

// ============================================================================
// QuantizedLinear: y[M,N] = x[M,K] @ Wq[N,K]^T * scale + bias
// M=16384, N=4096, K=4096.
// R4: fp16 two-plane HMMA (int8 IMMA measured 2x slower/instr -> reverted).
//   x = h + l/1024 with h=fp16(x), l=fp16((x-h)*1024); W exact in fp16.
//   hi plane: f32 accumulators; lo plane: f16 accumulators (half-rate probe).
//   Fragment double-buffering, early stage release, 4-stage bulk pipeline.
// ============================================================================

#define M_TOTAL  16384
#define N_TOTAL  4096
#define K_TOTAL  4096

#define TILE_M   128
#define TILE_N   128
#define TILE_K   64          // 64 fp16 = 128 bytes/row = SW128 atom width
#define NUM_KT   (K_TOTAL / TILE_K)   // 64
#define STAGES   4

#define A_TILE_BYTES  (TILE_M * TILE_K * 2)   // 16384 (per plane)
#define B_TILE_BYTES  (TILE_N * TILE_K * 2)   // 16384
#define STAGE_BYTES   (2 * A_TILE_BYTES + B_TILE_BYTES)  // 49152

#define TILES_M  (M_TOTAL / TILE_M)   // 128
#define TILES_N  (N_TOTAL / TILE_N)   // 32

#define LO_SCALE 1024.0f
#define INV_LO   (1.0f / 1024.0f)

// Scratch: pre-tiled, pre-swizzled operands (static device arrays, no allocs).
__device__ uint4 g_xh[(size_t)M_TOTAL * K_TOTAL / 8];   // 128 MB fp16 hi plane
__device__ uint4 g_xl[(size_t)M_TOTAL * K_TOTAL / 8];   // 128 MB fp16 lo plane
__device__ uint4 g_wh[(size_t)N_TOTAL * K_TOTAL / 8];   //  32 MB fp16 weights

// ---------------------------------------------------------------------------
// PTX helpers (base ISA only)
// ---------------------------------------------------------------------------
__device__ __forceinline__ uint32_t smem_u32(const void* p) {
    uint32_t a;
    asm("{ .reg .u64 t; cvta.to.shared.u64 t, %1; cvt.u32.u64 %0, t; }"
        : "=r"(a) : "l"(p));
    return a;
}
__device__ __forceinline__ void mbar_init(uint32_t mbar, uint32_t count) {
    asm volatile("mbarrier.init.shared.b64 [%0], %1;" :: "r"(mbar), "r"(count) : "memory");
}
__device__ __forceinline__ void mbar_expect_tx(uint32_t mbar, uint32_t bytes) {
    asm volatile("mbarrier.arrive.expect_tx.shared.b64 _, [%0], %1;"
                 :: "r"(mbar), "r"(bytes) : "memory");
}
__device__ __forceinline__ void mbar_arrive(uint32_t mbar) {
    asm volatile("mbarrier.arrive.shared.b64 _, [%0];" :: "r"(mbar) : "memory");
}
__device__ __forceinline__ void mbar_wait(uint32_t mbar, uint32_t parity) {
    asm volatile(
        "{\n\t.reg .pred P;\n\t"
        "WAITLOOP_%=:\n\t"
        "mbarrier.try_wait.parity.acquire.cta.shared::cta.b64 P, [%0], %1, 0x989680;\n\t"
        "@!P bra WAITLOOP_%=;\n\t}"
        :: "r"(mbar), "r"(parity) : "memory");
}
__device__ __forceinline__ void bulk_g2s(uint32_t dst, const void* src,
                                         uint32_t bytes, uint32_t mbar) {
    asm volatile(
        "cp.async.bulk.shared::cta.global.mbarrier::complete_tx::bytes [%0], [%1], %2, [%3];"
        :: "r"(dst), "l"(src), "r"(bytes), "r"(mbar) : "memory");
}
#define FENCE_PROXY_ASYNC() asm volatile("fence.proxy.async;" ::: "memory")

__device__ __forceinline__ void ldsm_x4(uint32_t* r, uint32_t addr) {
    asm volatile("ldmatrix.sync.aligned.m8n8.x4.shared.b16 {%0,%1,%2,%3}, [%4];"
                 : "=r"(r[0]), "=r"(r[1]), "=r"(r[2]), "=r"(r[3]) : "r"(addr));
}
// fp16 x fp16 -> fp32 accumulators
__device__ __forceinline__ void hmma_f32(float* c, const uint32_t* a, const uint32_t* b) {
    asm volatile(
        "mma.sync.aligned.m16n8k16.row.col.f32.f16.f16.f32 "
        "{%0,%1,%2,%3}, {%4,%5,%6,%7}, {%8,%9}, {%0,%1,%2,%3};"
        : "+f"(c[0]), "+f"(c[1]), "+f"(c[2]), "+f"(c[3])
        : "r"(a[0]), "r"(a[1]), "r"(a[2]), "r"(a[3]), "r"(b[0]), "r"(b[1]));
}
// fp16 x fp16 -> fp16 accumulators (2 x f16x2 regs)
__device__ __forceinline__ void hmma_f16(uint32_t* c, const uint32_t* a, const uint32_t* b) {
    asm volatile(
        "mma.sync.aligned.m16n8k16.row.col.f16.f16.f16.f16 "
        "{%0,%1}, {%2,%3,%4,%5}, {%6,%7}, {%0,%1};"
        : "+r"(c[0]), "+r"(c[1])
        : "r"(a[0]), "r"(a[1]), "r"(a[2]), "r"(a[3]), "r"(b[0]), "r"(b[1]));
}

__device__ __forceinline__ uint32_t sw128(uint32_t off) {
    return off ^ ((off >> 3) & 0x70);
}
__device__ __forceinline__ uint32_t pack_h2(__half a, __half b) {
    return (uint32_t)__half_as_ushort(a) | ((uint32_t)__half_as_ushort(b) << 16);
}

// ---------------------------------------------------------------------------
// Prep 1: split x (fp32) -> h, l (fp16), tiled [mt][kt][128x64] SW128.
// x = h + l/1024 with |x - (h + l/1024)| <= |x| * 2^-22.
// ---------------------------------------------------------------------------
__global__ void __launch_bounds__(256) split_x_kernel(const float* __restrict__ x) {
    uint32_t gid = blockIdx.x * 256u + threadIdx.x;   // M*K/8 threads
    int m  = gid >> 9;
    int k  = (gid & 511) << 3;

    const float4* xp = reinterpret_cast<const float4*>(x + ((size_t)m << 12) + k);
    float4 a = xp[0], b = xp[1];
    float f[8] = {a.x, a.y, a.z, a.w, b.x, b.y, b.z, b.w};

    uint32_t hi[4], lo[4];
#pragma unroll
    for (int i = 0; i < 4; i++) {
        __half h0 = __float2half_rn(f[2*i]);
        __half h1 = __float2half_rn(f[2*i+1]);
        __half l0 = __float2half_rn((f[2*i]   - __half2float(h0)) * LO_SCALE);
        __half l1 = __float2half_rn((f[2*i+1] - __half2float(h1)) * LO_SCALE);
        hi[i] = pack_h2(h0, h1);
        lo[i] = pack_h2(l0, l1);
    }

    int mt = m >> 7, row = m & 127, kt = k >> 6, kin = k & 63;
    size_t base = ((size_t)(mt * NUM_KT + kt)) * A_TILE_BYTES;
    uint32_t off = sw128((uint32_t)(row * 128 + kin * 2));

    *reinterpret_cast<uint4*>(reinterpret_cast<char*>(g_xh) + base + off) =
        make_uint4(hi[0], hi[1], hi[2], hi[3]);
    *reinterpret_cast<uint4*>(reinterpret_cast<char*>(g_xl) + base + off) =
        make_uint4(lo[0], lo[1], lo[2], lo[3]);
}

// ---------------------------------------------------------------------------
// Prep 2: weight int32 (0..126) -> fp16 (exact), tiled [nt][kt][128x64] SW128.
// ---------------------------------------------------------------------------
__global__ void __launch_bounds__(256) conv_w_kernel(const int* __restrict__ wq) {
    uint32_t gid = blockIdx.x * 256u + threadIdx.x;   // N*K/8 threads
    int n = gid >> 9;
    int k = (gid & 511) << 3;

    const int4* wp = reinterpret_cast<const int4*>(wq + ((size_t)n << 12) + k);
    int4 a = wp[0], b = wp[1];
    int v[8] = {a.x, a.y, a.z, a.w, b.x, b.y, b.z, b.w};

    uint32_t w[4];
#pragma unroll
    for (int i = 0; i < 4; i++) {
        w[i] = pack_h2(__int2half_rn(v[2*i]), __int2half_rn(v[2*i+1]));
    }

    int nt = n >> 7, row = n & 127, kt = k >> 6, kin = k & 63;
    size_t base = ((size_t)(nt * NUM_KT + kt)) * B_TILE_BYTES;
    uint32_t off = sw128((uint32_t)(row * 128 + kin * 2));

    *reinterpret_cast<uint4*>(reinterpret_cast<char*>(g_wh) + base + off) =
        make_uint4(w[0], w[1], w[2], w[3]);
}

// ---------------------------------------------------------------------------
// GEMM: 128x128 output tile per CTA. 8 consumer warps (32x64 each, 4Mx2N),
// 1 producer warp. 4-stage bulk-copy pipeline, fragment double-buffering.
// ---------------------------------------------------------------------------
#define NTHREADS      288
#define SMEM_RAW_BYTES (1024 + 1024 + STAGES * STAGE_BYTES)   // 198656

__global__ void __launch_bounds__(NTHREADS, 1)
gemm_kernel(float* __restrict__ out, const float* __restrict__ scale,
            const float* __restrict__ bias) {
    extern __shared__ char smem_raw[];
    uint32_t sb = (smem_u32(smem_raw) + 1023u) & ~1023u;

    const int tid = threadIdx.x;
    const int wid = tid >> 5;
    const int lid = tid & 31;

    // L2-friendly tile grouping: 4 m-tiles x 32 n-tiles per group of 128 CTAs
    int bid = blockIdx.x;
    int grp = bid >> 7;
    int r   = bid & 127;
    int mt  = (grp << 2) + (r & 3);
    int nt  = r >> 2;

    const uint32_t FULL_BAR  = sb;          // 4 x 8B
    const uint32_t EMPTY_BAR = sb + 64;     // 4 x 8B
    const uint32_t DATA      = sb + 1024;

    if (tid == 0) {
#pragma unroll
        for (int s = 0; s < STAGES; s++) {
            mbar_init(FULL_BAR  + s * 8, 1);
            mbar_init(EMPTY_BAR + s * 8, 8);
        }
        FENCE_PROXY_ASYNC();
    }
    __syncthreads();

    // ---------------- Producer warp ----------------
    if (wid == 8) {
        if (lid == 0) {
            const char* xh = reinterpret_cast<const char*>(g_xh) +
                             (size_t)mt * NUM_KT * A_TILE_BYTES;
            const char* xl = reinterpret_cast<const char*>(g_xl) +
                             (size_t)mt * NUM_KT * A_TILE_BYTES;
            const char* wh = reinterpret_cast<const char*>(g_wh) +
                             (size_t)nt * NUM_KT * B_TILE_BYTES;

            auto issue = [&](int s, int kt) {
                uint32_t fb = FULL_BAR + s * 8;
                uint32_t d  = DATA + s * STAGE_BYTES;
                mbar_expect_tx(fb, STAGE_BYTES);
                bulk_g2s(d,                    xh + (size_t)kt * A_TILE_BYTES, A_TILE_BYTES, fb);
                bulk_g2s(d + A_TILE_BYTES,     xl + (size_t)kt * A_TILE_BYTES, A_TILE_BYTES, fb);
                bulk_g2s(d + 2 * A_TILE_BYTES, wh + (size_t)kt * B_TILE_BYTES, B_TILE_BYTES, fb);
            };

            issue(0, 0); issue(1, 1); issue(2, 2); issue(3, 3);
            int ep[STAGES] = {0, 0, 0, 0};
            for (int kt = STAGES; kt < NUM_KT; kt++) {
                int s = kt % STAGES;
                mbar_wait(EMPTY_BAR + s * 8, ep[s]); ep[s] ^= 1;
                issue(s, kt);
            }
        }
        return;
    }

    // ---------------- Consumer warps ----------------
    const int warp_m = wid & 3;          // 4 warps over M: 32 rows each
    const int warp_n = wid >> 2;         // 2 warps over N: 64 cols each

    // Per-lane swizzled SMEM offsets (kstep 0). K advance = XOR ks*32.
    uint32_t a_off[2], b_off[4];
#pragma unroll
    for (int mf = 0; mf < 2; mf++) {
        int row = warp_m * 32 + mf * 16 + (lid & 15);
        a_off[mf] = sw128((uint32_t)(row * 128 + (lid >> 4) * 16));
    }
#pragma unroll
    for (int p = 0; p < 4; p++) {
        int nrow = warp_n * 64 + p * 16 + (lid & 7) + ((lid >> 4) & 1) * 8;
        b_off[p] = sw128((uint32_t)(nrow * 128 + ((lid >> 3) & 1) * 16));
    }

    float    acch[2][8][4];   // hi plane, fp32 accum
    uint32_t accl[2][8][2];   // lo plane, fp16 accum (f16x2 pairs)
#pragma unroll
    for (int mf = 0; mf < 2; mf++)
#pragma unroll
        for (int nf = 0; nf < 8; nf++) {
#pragma unroll
            for (int i = 0; i < 4; i++) acch[mf][nf][i] = 0.f;
            accl[mf][nf][0] = 0u; accl[mf][nf][1] = 0u;
        }

    // Double-buffered fragments
    uint32_t fh[2][2][4], fl[2][2][4], fb[2][4][4];
    int fp[STAGES] = {0, 0, 0, 0};

#pragma unroll 1
    for (int kt = 0; kt < NUM_KT; kt++) {
        int s = kt % STAGES;
        mbar_wait(FULL_BAR + s * 8, fp[s]); fp[s] ^= 1;

        uint32_t ah = DATA + s * STAGE_BYTES;
        uint32_t al = ah + A_TILE_BYTES;
        uint32_t bb = al + A_TILE_BYTES;

        auto load_frags = [&](int buf, int ks) {
            uint32_t kb = (uint32_t)ks * 32;
            ldsm_x4(fh[buf][0], ah + (a_off[0] ^ kb));
            ldsm_x4(fh[buf][1], ah + (a_off[1] ^ kb));
            ldsm_x4(fl[buf][0], al + (a_off[0] ^ kb));
            ldsm_x4(fl[buf][1], al + (a_off[1] ^ kb));
            ldsm_x4(fb[buf][0], bb + (b_off[0] ^ kb));
            ldsm_x4(fb[buf][1], bb + (b_off[1] ^ kb));
            ldsm_x4(fb[buf][2], bb + (b_off[2] ^ kb));
            ldsm_x4(fb[buf][3], bb + (b_off[3] ^ kb));
        };
        auto do_mma = [&](int buf) {
#pragma unroll
            for (int mf = 0; mf < 2; mf++)
#pragma unroll
                for (int nf = 0; nf < 8; nf++) {
                    const uint32_t* bp = &fb[buf][nf >> 1][(nf & 1) * 2];
                    hmma_f32(acch[mf][nf], fh[buf][mf], bp);
                    hmma_f16(accl[mf][nf], fl[buf][mf], bp);
                }
        };

        load_frags(0, 0);
        load_frags(1, 1);
        do_mma(0);
        load_frags(0, 2);
        do_mma(1);
        load_frags(1, 3);
        do_mma(0);
        // All SMEM reads for this stage issued and long retired by now:
        // release the stage before the last MMA block.
        __syncwarp();
        if (lid == 0) mbar_arrive(EMPTY_BAR + s * 8);
        do_mma(1);
    }

    // -------- Epilogue: y = scale*(acc_hi + acc_lo/1024) + bias --------
    float scl = __ldg(scale);
    int row0 = (mt << 7) + warp_m * 32 + (lid >> 2);
    int col0 = (nt << 7) + warp_n * 64 + (lid & 3) * 2;

#pragma unroll
    for (int nf = 0; nf < 8; nf++) {
        int col = col0 + nf * 8;
        float2 bv = __ldg(reinterpret_cast<const float2*>(bias + col));
#pragma unroll
        for (int mf = 0; mf < 2; mf++) {
            int ra = row0 + mf * 16;
            float2 l01 = __half22float2(
                *reinterpret_cast<const __half2*>(&accl[mf][nf][0]));
            float2 l23 = __half22float2(
                *reinterpret_cast<const __half2*>(&accl[mf][nf][1]));
            float2 o0, o1;
            o0.x = scl * (acch[mf][nf][0] + l01.x * INV_LO) + bv.x;
            o0.y = scl * (acch[mf][nf][1] + l01.y * INV_LO) + bv.y;
            o1.x = scl * (acch[mf][nf][2] + l23.x * INV_LO) + bv.x;
            o1.y = scl * (acch[mf][nf][3] + l23.y * INV_LO) + bv.y;
            *reinterpret_cast<float2*>(out + ((size_t)ra << 12)       + col) = o0;
            *reinterpret_cast<float2*>(out + ((size_t)(ra + 8) << 12) + col) = o1;
        }
    }
}

// ---------------------------------------------------------------------------
// Launch
// ---------------------------------------------------------------------------
extern "C" void kernel_launch(void* const* d_in, const int* in_sizes, int n_in,
                              void* d_out, int out_size) {
    const float* x     = (const float*)d_in[0];   // [4,4096,4096] fp32
    const int*   wq    = (const int*)  d_in[1];   // [4096,4096]   int32
    const float* scale = (const float*)d_in[2];   // [1]           fp32
    const float* bias  = (const float*)d_in[3];   // [4096]        fp32
    float*       out   = (float*)d_out;           // [4,4096,4096] fp32

    split_x_kernel<<<(M_TOTAL * (K_TOTAL / 8)) / 256, 256>>>(x);
    conv_w_kernel <<<(N_TOTAL * (K_TOTAL / 8)) / 256, 256>>>(wq);

    cudaFuncSetAttribute(gemm_kernel, cudaFuncAttributeMaxDynamicSharedMemorySize,
                         SMEM_RAW_BYTES);
    gemm_kernel<<<TILES_M * TILES_N, NTHREADS, SMEM_RAW_BYTES>>>(out, scale, bias);
}

// round 6
// speedup vs baseline: 5.6245x; 1.6262x over previous
#include <cuda_runtime.h>
#include <cuda_fp16.h>
#include <cstdint>

// ============================================================================
// QuantizedLinear: y[M,N] = x[M,K] @ Wq[N,K]^T * scale + bias
// M=16384, N=4096, K=4096.
// R5: SINGLE-plane fp16 HMMA (f32 accum).
//   Error budget: fp16 rounding of x -> ~3.5e-4 rel (threshold 1e-3).
//   W (ints <=126) exact in fp16; fp16xfp16 products exact in f32.
//   2 CTAs/SM (3-stage pipeline each) to hide epilogue/waits.
// ============================================================================

#define M_TOTAL  16384
#define N_TOTAL  4096
#define K_TOTAL  4096

#define TILE_M   128
#define TILE_N   128
#define TILE_K   64          // 64 fp16 = 128 bytes/row = SW128 atom width
#define NUM_KT   (K_TOTAL / TILE_K)   // 64
#define STAGES   3

#define A_TILE_BYTES  (TILE_M * TILE_K * 2)   // 16384
#define B_TILE_BYTES  (TILE_N * TILE_K * 2)   // 16384
#define STAGE_BYTES   (A_TILE_BYTES + B_TILE_BYTES)   // 32768

#define TILES_M  (M_TOTAL / TILE_M)   // 128
#define TILES_N  (N_TOTAL / TILE_N)   // 32

// Scratch: pre-tiled, pre-swizzled operands (static device arrays, no allocs).
__device__ uint4 g_xh[(size_t)M_TOTAL * K_TOTAL / 8];   // 128 MB fp16 x
__device__ uint4 g_wh[(size_t)N_TOTAL * K_TOTAL / 8];   //  32 MB fp16 weights

// ---------------------------------------------------------------------------
// PTX helpers (base ISA only)
// ---------------------------------------------------------------------------
__device__ __forceinline__ uint32_t smem_u32(const void* p) {
    uint32_t a;
    asm("{ .reg .u64 t; cvta.to.shared.u64 t, %1; cvt.u32.u64 %0, t; }"
        : "=r"(a) : "l"(p));
    return a;
}
__device__ __forceinline__ void mbar_init(uint32_t mbar, uint32_t count) {
    asm volatile("mbarrier.init.shared.b64 [%0], %1;" :: "r"(mbar), "r"(count) : "memory");
}
__device__ __forceinline__ void mbar_expect_tx(uint32_t mbar, uint32_t bytes) {
    asm volatile("mbarrier.arrive.expect_tx.shared.b64 _, [%0], %1;"
                 :: "r"(mbar), "r"(bytes) : "memory");
}
__device__ __forceinline__ void mbar_arrive(uint32_t mbar) {
    asm volatile("mbarrier.arrive.shared.b64 _, [%0];" :: "r"(mbar) : "memory");
}
__device__ __forceinline__ void mbar_wait(uint32_t mbar, uint32_t parity) {
    asm volatile(
        "{\n\t.reg .pred P;\n\t"
        "WAITLOOP_%=:\n\t"
        "mbarrier.try_wait.parity.acquire.cta.shared::cta.b64 P, [%0], %1, 0x989680;\n\t"
        "@!P bra WAITLOOP_%=;\n\t}"
        :: "r"(mbar), "r"(parity) : "memory");
}
__device__ __forceinline__ void bulk_g2s(uint32_t dst, const void* src,
                                         uint32_t bytes, uint32_t mbar) {
    asm volatile(
        "cp.async.bulk.shared::cta.global.mbarrier::complete_tx::bytes [%0], [%1], %2, [%3];"
        :: "r"(dst), "l"(src), "r"(bytes), "r"(mbar) : "memory");
}
#define FENCE_PROXY_ASYNC() asm volatile("fence.proxy.async;" ::: "memory")

__device__ __forceinline__ void ldsm_x4(uint32_t* r, uint32_t addr) {
    asm volatile("ldmatrix.sync.aligned.m8n8.x4.shared.b16 {%0,%1,%2,%3}, [%4];"
                 : "=r"(r[0]), "=r"(r[1]), "=r"(r[2]), "=r"(r[3]) : "r"(addr));
}
__device__ __forceinline__ void hmma_f32(float* c, const uint32_t* a, const uint32_t* b) {
    asm volatile(
        "mma.sync.aligned.m16n8k16.row.col.f32.f16.f16.f32 "
        "{%0,%1,%2,%3}, {%4,%5,%6,%7}, {%8,%9}, {%0,%1,%2,%3};"
        : "+f"(c[0]), "+f"(c[1]), "+f"(c[2]), "+f"(c[3])
        : "r"(a[0]), "r"(a[1]), "r"(a[2]), "r"(a[3]), "r"(b[0]), "r"(b[1]));
}

__device__ __forceinline__ uint32_t sw128(uint32_t off) {
    return off ^ ((off >> 3) & 0x70);
}
__device__ __forceinline__ uint32_t pack_h2(__half a, __half b) {
    return (uint32_t)__half_as_ushort(a) | ((uint32_t)__half_as_ushort(b) << 16);
}

// ---------------------------------------------------------------------------
// Prep 1: x (fp32) -> fp16, tiled [mt][kt][128x64] SW128.
// ---------------------------------------------------------------------------
__global__ void __launch_bounds__(256) split_x_kernel(const float* __restrict__ x) {
    uint32_t gid = blockIdx.x * 256u + threadIdx.x;   // M*K/8 threads
    int m  = gid >> 9;
    int k  = (gid & 511) << 3;

    const float4* xp = reinterpret_cast<const float4*>(x + ((size_t)m << 12) + k);
    float4 a = xp[0], b = xp[1];
    float f[8] = {a.x, a.y, a.z, a.w, b.x, b.y, b.z, b.w};

    uint32_t hi[4];
#pragma unroll
    for (int i = 0; i < 4; i++) {
        hi[i] = pack_h2(__float2half_rn(f[2*i]), __float2half_rn(f[2*i+1]));
    }

    int mt = m >> 7, row = m & 127, kt = k >> 6, kin = k & 63;
    size_t base = ((size_t)(mt * NUM_KT + kt)) * A_TILE_BYTES;
    uint32_t off = sw128((uint32_t)(row * 128 + kin * 2));

    *reinterpret_cast<uint4*>(reinterpret_cast<char*>(g_xh) + base + off) =
        make_uint4(hi[0], hi[1], hi[2], hi[3]);
}

// ---------------------------------------------------------------------------
// Prep 2: weight int32 (0..126) -> fp16 (exact), tiled [nt][kt][128x64] SW128.
// ---------------------------------------------------------------------------
__global__ void __launch_bounds__(256) conv_w_kernel(const int* __restrict__ wq) {
    uint32_t gid = blockIdx.x * 256u + threadIdx.x;   // N*K/8 threads
    int n = gid >> 9;
    int k = (gid & 511) << 3;

    const int4* wp = reinterpret_cast<const int4*>(wq + ((size_t)n << 12) + k);
    int4 a = wp[0], b = wp[1];
    int v[8] = {a.x, a.y, a.z, a.w, b.x, b.y, b.z, b.w};

    uint32_t w[4];
#pragma unroll
    for (int i = 0; i < 4; i++) {
        w[i] = pack_h2(__int2half_rn(v[2*i]), __int2half_rn(v[2*i+1]));
    }

    int nt = n >> 7, row = n & 127, kt = k >> 6, kin = k & 63;
    size_t base = ((size_t)(nt * NUM_KT + kt)) * B_TILE_BYTES;
    uint32_t off = sw128((uint32_t)(row * 128 + kin * 2));

    *reinterpret_cast<uint4*>(reinterpret_cast<char*>(g_wh) + base + off) =
        make_uint4(w[0], w[1], w[2], w[3]);
}

// ---------------------------------------------------------------------------
// GEMM: 128x128 output tile per CTA. 8 consumer warps (32x64 each, 4Mx2N),
// 1 producer warp. 3-stage pipeline, 2 CTAs per SM.
// ---------------------------------------------------------------------------
#define NTHREADS      288
#define SMEM_RAW_BYTES (1024 + 1024 + STAGES * STAGE_BYTES)   // 100352

__global__ void __launch_bounds__(NTHREADS, 2)
gemm_kernel(float* __restrict__ out, const float* __restrict__ scale,
            const float* __restrict__ bias) {
    extern __shared__ char smem_raw[];
    uint32_t sb = (smem_u32(smem_raw) + 1023u) & ~1023u;

    const int tid = threadIdx.x;
    const int wid = tid >> 5;
    const int lid = tid & 31;

    // L2-friendly tile grouping: 4 m-tiles x 32 n-tiles per group of 128 CTAs
    int bid = blockIdx.x;
    int grp = bid >> 7;
    int r   = bid & 127;
    int mt  = (grp << 2) + (r & 3);
    int nt  = r >> 2;

    const uint32_t FULL_BAR  = sb;          // 3 x 8B
    const uint32_t EMPTY_BAR = sb + 32;     // 3 x 8B
    const uint32_t DATA      = sb + 1024;

    if (tid == 0) {
#pragma unroll
        for (int s = 0; s < STAGES; s++) {
            mbar_init(FULL_BAR  + s * 8, 1);
            mbar_init(EMPTY_BAR + s * 8, 8);
        }
        FENCE_PROXY_ASYNC();
    }
    __syncthreads();

    // ---------------- Producer warp ----------------
    if (wid == 8) {
        if (lid == 0) {
            const char* xh = reinterpret_cast<const char*>(g_xh) +
                             (size_t)mt * NUM_KT * A_TILE_BYTES;
            const char* wh = reinterpret_cast<const char*>(g_wh) +
                             (size_t)nt * NUM_KT * B_TILE_BYTES;

            auto issue = [&](int s, int kt) {
                uint32_t fb = FULL_BAR + s * 8;
                uint32_t d  = DATA + s * STAGE_BYTES;
                mbar_expect_tx(fb, STAGE_BYTES);
                bulk_g2s(d,                xh + (size_t)kt * A_TILE_BYTES, A_TILE_BYTES, fb);
                bulk_g2s(d + A_TILE_BYTES, wh + (size_t)kt * B_TILE_BYTES, B_TILE_BYTES, fb);
            };

            issue(0, 0); issue(1, 1); issue(2, 2);
            int ep[STAGES] = {0, 0, 0};
            for (int kt = STAGES; kt < NUM_KT; kt++) {
                int s = kt % STAGES;
                mbar_wait(EMPTY_BAR + s * 8, ep[s]); ep[s] ^= 1;
                issue(s, kt);
            }
        }
        return;
    }

    // ---------------- Consumer warps ----------------
    const int warp_m = wid & 3;          // 4 warps over M: 32 rows each
    const int warp_n = wid >> 2;         // 2 warps over N: 64 cols each

    // Per-lane swizzled SMEM offsets (kstep 0). K advance = XOR ks*32.
    uint32_t a_off[2], b_off[4];
#pragma unroll
    for (int mf = 0; mf < 2; mf++) {
        int row = warp_m * 32 + mf * 16 + (lid & 15);
        a_off[mf] = sw128((uint32_t)(row * 128 + (lid >> 4) * 16));
    }
#pragma unroll
    for (int p = 0; p < 4; p++) {
        int nrow = warp_n * 64 + p * 16 + (lid & 7) + ((lid >> 4) & 1) * 8;
        b_off[p] = sw128((uint32_t)(nrow * 128 + ((lid >> 3) & 1) * 16));
    }

    float acch[2][8][4];
#pragma unroll
    for (int mf = 0; mf < 2; mf++)
#pragma unroll
        for (int nf = 0; nf < 8; nf++)
#pragma unroll
            for (int i = 0; i < 4; i++) acch[mf][nf][i] = 0.f;

    int fp[STAGES] = {0, 0, 0};

#pragma unroll 1
    for (int kt = 0; kt < NUM_KT; kt++) {
        int s = kt % STAGES;
        mbar_wait(FULL_BAR + s * 8, fp[s]); fp[s] ^= 1;

        uint32_t ah = DATA + s * STAGE_BYTES;
        uint32_t bb = ah + A_TILE_BYTES;

#pragma unroll
        for (int ks = 0; ks < 4; ks++) {
            uint32_t kb = (uint32_t)ks * 32;   // XOR into swizzled offset
            uint32_t fa[2][4], fbr[4][4];
            ldsm_x4(fa[0],  ah + (a_off[0] ^ kb));
            ldsm_x4(fa[1],  ah + (a_off[1] ^ kb));
            ldsm_x4(fbr[0], bb + (b_off[0] ^ kb));
            ldsm_x4(fbr[1], bb + (b_off[1] ^ kb));
            ldsm_x4(fbr[2], bb + (b_off[2] ^ kb));
            ldsm_x4(fbr[3], bb + (b_off[3] ^ kb));

            if (ks == 3) {               // all stage reads issued: early release
                __syncwarp();
                if (lid == 0) mbar_arrive(EMPTY_BAR + s * 8);
            }

#pragma unroll
            for (int mf = 0; mf < 2; mf++)
#pragma unroll
                for (int nf = 0; nf < 8; nf++) {
                    hmma_f32(acch[mf][nf], fa[mf], &fbr[nf >> 1][(nf & 1) * 2]);
                }
        }
    }

    // -------- Epilogue: y = scale*acc + bias --------
    float scl = __ldg(scale);
    int row0 = (mt << 7) + warp_m * 32 + (lid >> 2);
    int col0 = (nt << 7) + warp_n * 64 + (lid & 3) * 2;

#pragma unroll
    for (int nf = 0; nf < 8; nf++) {
        int col = col0 + nf * 8;
        float2 bv = __ldg(reinterpret_cast<const float2*>(bias + col));
#pragma unroll
        for (int mf = 0; mf < 2; mf++) {
            int ra = row0 + mf * 16;
            float2 o0, o1;
            o0.x = scl * acch[mf][nf][0] + bv.x;
            o0.y = scl * acch[mf][nf][1] + bv.y;
            o1.x = scl * acch[mf][nf][2] + bv.x;
            o1.y = scl * acch[mf][nf][3] + bv.y;
            *reinterpret_cast<float2*>(out + ((size_t)ra << 12)       + col) = o0;
            *reinterpret_cast<float2*>(out + ((size_t)(ra + 8) << 12) + col) = o1;
        }
    }
}

// ---------------------------------------------------------------------------
// Launch
// ---------------------------------------------------------------------------
extern "C" void kernel_launch(void* const* d_in, const int* in_sizes, int n_in,
                              void* d_out, int out_size) {
    const float* x     = (const float*)d_in[0];   // [4,4096,4096] fp32
    const int*   wq    = (const int*)  d_in[1];   // [4096,4096]   int32
    const float* scale = (const float*)d_in[2];   // [1]           fp32
    const float* bias  = (const float*)d_in[3];   // [4096]        fp32
    float*       out   = (float*)d_out;           // [4,4096,4096] fp32

    split_x_kernel<<<(M_TOTAL * (K_TOTAL / 8)) / 256, 256>>>(x);
    conv_w_kernel <<<(N_TOTAL * (K_TOTAL / 8)) / 256, 256>>>(wq);

    cudaFuncSetAttribute(gemm_kernel, cudaFuncAttributeMaxDynamicSharedMemorySize,
                         SMEM_RAW_BYTES);
    gemm_kernel<<<TILES_M * TILES_N, NTHREADS, SMEM_RAW_BYTES>>>(out, scale, bias);
}